// round 1
// baseline (speedup 1.0000x reference)
#include <cuda_runtime.h>

#define VSZ 32000
#define ESZ 256
#define HSZ 256
#define BSZ 256
#define SSZ 512
#define OSZ 32000

// Scratch: E_proj [V, 3H] fp32 (emb @ [Wz;Wr;Wh]^T + all biases folded), and final h.
__device__ float g_eproj[(size_t)VSZ * 768];
__device__ float g_hlast[BSZ * HSZ];

// ---- packed f32x2 helpers (Blackwell sm_103a) ----
__device__ __forceinline__ unsigned long long pk2(float lo, float hi) {
    unsigned long long r;
    asm("mov.b64 %0, {%1, %2};" : "=l"(r) : "f"(lo), "f"(hi));
    return r;
}
__device__ __forceinline__ void fma2(unsigned long long& d, unsigned long long a,
                                     unsigned long long b) {
    asm("fma.rn.f32x2 %0, %1, %2, %0;" : "+l"(d) : "l"(a), "l"(b));
}
__device__ __forceinline__ float hsum2(unsigned long long v) {
    float lo, hi;
    asm("mov.b64 {%0, %1}, %2;" : "=f"(lo), "=f"(hi) : "l"(v));
    return lo + hi;
}
__device__ __forceinline__ float sigm(float x) { return 1.0f / (1.0f + __expf(-x)); }

// ============================================================================
// SGEMM-NT with bias: C[row, coloff+col] = dot(A[row,:], Bw[col,:]) + bias1[col] (+ bias2[col])
// A: [M,256] row-major, Bw: [N,256] row-major. Tiles 128x128, K-chunk 16,
// 256 threads, 8x8 micro-tile on packed f32x2.
// Requires M%128==0, N%128==0 (true for all call sites: 32000, 256).
// ============================================================================
__global__ void __launch_bounds__(256) sgemm_nt_bias(
    const float* __restrict__ A, const float* __restrict__ Bw,
    const float* __restrict__ bias1, const float* __restrict__ bias2,
    float* __restrict__ C, int ldc, int coloff)
{
    __shared__ __align__(16) float As[16][132];
    __shared__ __align__(16) float Bs[16][132];
    const int t  = threadIdx.x;
    const int tm = t >> 4;       // 0..15
    const int tn = t & 15;       // 0..15

    unsigned long long acc[8][4];
#pragma unroll
    for (int i = 0; i < 8; i++)
#pragma unroll
        for (int j = 0; j < 4; j++) acc[i][j] = 0ULL;

    const float* Ab = A  + (size_t)blockIdx.x * 128 * 256;
    const float* Bb = Bw + (size_t)blockIdx.y * 128 * 256;
    const int lr = t >> 2;            // 0..63
    const int lk = (t & 3) << 2;      // 0,4,8,12

    for (int k0 = 0; k0 < 256; k0 += 16) {
        float4 a0 = *(const float4*)(Ab + (size_t)lr * 256 + k0 + lk);
        float4 a1 = *(const float4*)(Ab + (size_t)(lr + 64) * 256 + k0 + lk);
        float4 b0 = *(const float4*)(Bb + (size_t)lr * 256 + k0 + lk);
        float4 b1 = *(const float4*)(Bb + (size_t)(lr + 64) * 256 + k0 + lk);
        __syncthreads();
        As[lk + 0][lr] = a0.x; As[lk + 1][lr] = a0.y;
        As[lk + 2][lr] = a0.z; As[lk + 3][lr] = a0.w;
        As[lk + 0][lr + 64] = a1.x; As[lk + 1][lr + 64] = a1.y;
        As[lk + 2][lr + 64] = a1.z; As[lk + 3][lr + 64] = a1.w;
        Bs[lk + 0][lr] = b0.x; Bs[lk + 1][lr] = b0.y;
        Bs[lk + 2][lr] = b0.z; Bs[lk + 3][lr] = b0.w;
        Bs[lk + 0][lr + 64] = b1.x; Bs[lk + 1][lr + 64] = b1.y;
        Bs[lk + 2][lr + 64] = b1.z; Bs[lk + 3][lr + 64] = b1.w;
        __syncthreads();
#pragma unroll
        for (int kk = 0; kk < 16; kk++) {
            float4 av0 = *(const float4*)(&As[kk][tm * 8]);
            float4 av1 = *(const float4*)(&As[kk][tm * 8 + 4]);
            const unsigned long long* bp =
                (const unsigned long long*)(&Bs[kk][tn * 8]);
            unsigned long long b2_0 = bp[0], b2_1 = bp[1], b2_2 = bp[2], b2_3 = bp[3];
            float av[8] = {av0.x, av0.y, av0.z, av0.w, av1.x, av1.y, av1.z, av1.w};
#pragma unroll
            for (int i = 0; i < 8; i++) {
                unsigned long long a2 = pk2(av[i], av[i]);
                fma2(acc[i][0], a2, b2_0);
                fma2(acc[i][1], a2, b2_1);
                fma2(acc[i][2], a2, b2_2);
                fma2(acc[i][3], a2, b2_3);
            }
        }
    }

    const int row0 = blockIdx.x * 128 + tm * 8;
    const int col0 = blockIdx.y * 128 + tn * 8;
#pragma unroll
    for (int i = 0; i < 8; i++) {
#pragma unroll
        for (int j = 0; j < 4; j++) {
            float lo, hi;
            asm("mov.b64 {%0, %1}, %2;" : "=f"(lo), "=f"(hi) : "l"(acc[i][j]));
            int n0 = col0 + j * 2;
            float e0 = bias1[n0]     + (bias2 ? bias2[n0]     : 0.0f);
            float e1 = bias1[n0 + 1] + (bias2 ? bias2[n0 + 1] : 0.0f);
            C[(size_t)(row0 + i) * ldc + coloff + n0]     = lo + e0;
            C[(size_t)(row0 + i) * ldc + coloff + n0 + 1] = hi + e1;
        }
    }
}

// ============================================================================
// GRU scan: persistent, batch-partitioned (64 CTAs x 4 rows), NO inter-CTA sync.
// Thread j owns column j of z, r, h_tilde, h for its CTA's 4 batch rows.
// h kept in SMEM fp32; U streamed from L2 each step as packed f32x2 pairs.
// ============================================================================
__global__ void __launch_bounds__(256) gru_scan(
    const int* __restrict__ x,
    const float* __restrict__ Uz, const float* __restrict__ Ur,
    const float* __restrict__ Uh)
{
    __shared__ __align__(16) float sh[4][256];   // h state
    __shared__ __align__(16) float srh[4][256];  // r * h
    const int j  = threadIdx.x;                  // column 0..255
    const int b0 = blockIdx.x * 4;

#pragma unroll
    for (int m = 0; m < 4; m++) sh[m][j] = 0.0f;
    __syncthreads();

    const float* Uzr = Uz + (size_t)j * 256;     // row j of each U
    const float* Urr = Ur + (size_t)j * 256;
    const float* Uhr = Uh + (size_t)j * 256;

    for (int s = 0; s < SSZ; s++) {
        // token gather (broadcast across threads -> L1 hits)
        const float* ep[4];
#pragma unroll
        for (int m = 0; m < 4; m++) {
            int tok = __ldg(&x[(size_t)(b0 + m) * SSZ + s]);
            ep[m] = g_eproj + (size_t)tok * 768;
        }

        // -------- phase 1: z, r pre-activations (packed over k-pairs) --------
        unsigned long long az2[4], ar2[4];
#pragma unroll
        for (int m = 0; m < 4; m++) {
            az2[m] = pk2(ep[m][j], 0.0f);
            ar2[m] = pk2(ep[m][256 + j], 0.0f);
        }
#pragma unroll 8
        for (int k = 0; k < 256; k += 4) {
            ulonglong2 uz = *(const ulonglong2*)(Uzr + k);
            ulonglong2 ur = *(const ulonglong2*)(Urr + k);
#pragma unroll
            for (int m = 0; m < 4; m++) {
                ulonglong2 hp = *(const ulonglong2*)(&sh[m][k]);
                fma2(az2[m], uz.x, hp.x);
                fma2(az2[m], uz.y, hp.y);
                fma2(ar2[m], ur.x, hp.x);
                fma2(ar2[m], ur.y, hp.y);
            }
        }

        float zz[4], hcur[4];
#pragma unroll
        for (int m = 0; m < 4; m++) {
            zz[m]   = sigm(hsum2(az2[m]));
            float r = sigm(hsum2(ar2[m]));
            hcur[m] = sh[m][j];
            srh[m][j] = r * hcur[m];
        }
        __syncthreads();   // srh complete before phase-2 reads

        // -------- phase 2: h_tilde and state update --------
        unsigned long long ah2[4];
#pragma unroll
        for (int m = 0; m < 4; m++) ah2[m] = pk2(ep[m][512 + j], 0.0f);
#pragma unroll 8
        for (int k = 0; k < 256; k += 4) {
            ulonglong2 uh = *(const ulonglong2*)(Uhr + k);
#pragma unroll
            for (int m = 0; m < 4; m++) {
                ulonglong2 rp = *(const ulonglong2*)(&srh[m][k]);
                fma2(ah2[m], uh.x, rp.x);
                fma2(ah2[m], uh.y, rp.y);
            }
        }
#pragma unroll
        for (int m = 0; m < 4; m++) {
            float ht = tanhf(hsum2(ah2[m]));
            sh[m][j] = (1.0f - zz[m]) * hcur[m] + zz[m] * ht;
        }
        __syncthreads();   // h update visible before next step's phase 1
    }

#pragma unroll
    for (int m = 0; m < 4; m++)
        g_hlast[(size_t)(b0 + m) * HSZ + j] = sh[m][j];
}

// ============================================================================
extern "C" void kernel_launch(void* const* d_in, const int* in_sizes, int n_in,
                              void* d_out, int out_size)
{
    const int*   x   = (const int*)  d_in[0];
    const float* emb = (const float*)d_in[1];
    const float* Wz  = (const float*)d_in[2];
    const float* bz  = (const float*)d_in[3];
    const float* Uz  = (const float*)d_in[4];
    const float* buz = (const float*)d_in[5];
    const float* Wr  = (const float*)d_in[6];
    const float* br  = (const float*)d_in[7];
    const float* Ur  = (const float*)d_in[8];
    const float* bur = (const float*)d_in[9];
    const float* Wh  = (const float*)d_in[10];
    const float* bh  = (const float*)d_in[11];
    const float* Uh  = (const float*)d_in[12];
    const float* buh = (const float*)d_in[13];
    const float* Wf  = (const float*)d_in[14];
    const float* bf  = (const float*)d_in[15];
    float* out = (float*)d_out;

    float* eproj = nullptr;
    float* hlast = nullptr;
    cudaGetSymbolAddress((void**)&eproj, g_eproj);
    cudaGetSymbolAddress((void**)&hlast, g_hlast);

    dim3 blk(256);
    // E_proj = emb @ Wg^T + bg + bug, per gate (M=32000 -> 250 tiles, N=256 -> 2 tiles)
    sgemm_nt_bias<<<dim3(250, 2), blk>>>(emb, Wz, bz, buz, eproj, 768, 0);
    sgemm_nt_bias<<<dim3(250, 2), blk>>>(emb, Wr, br, bur, eproj, 768, 256);
    sgemm_nt_bias<<<dim3(250, 2), blk>>>(emb, Wh, bh, buh, eproj, 768, 512);

    // Recurrence: 64 CTAs x 4 batch rows, 512 steps, no inter-CTA sync
    gru_scan<<<64, blk>>>(x, Uz, Ur, Uh);

    // Logits: out = h_last @ Wf^T + bf  (M=256 -> 2 tiles, N=32000 -> 250 tiles)
    sgemm_nt_bias<<<dim3(2, 250), blk>>>(hlast, Wf, bf, nullptr, out, 32000, 0);
}

// round 2
// speedup vs baseline: 3.3590x; 3.3590x over previous
#include <cuda_runtime.h>

#define VSZ 32000
#define HSZ 256
#define BSZ 256
#define SSZ 512

typedef unsigned long long ull;

// Scratch (device globals; no allocation allowed)
__device__ float g_eproj[(size_t)VSZ * 768];   // emb @ [Wz;Wr;Wh]^T + biases
__device__ float g_hlast[BSZ * HSZ];
__device__ float g_uT[3 * 256 * 256];          // transposed U: uT[g][k][j]

// ---- packed f32x2 helpers (Blackwell sm_103a) ----
__device__ __forceinline__ ull pk2(float lo, float hi) {
    ull r;
    asm("mov.b64 %0, {%1, %2};" : "=l"(r) : "f"(lo), "f"(hi));
    return r;
}
__device__ __forceinline__ void fma2(ull& d, ull a, ull b) {
    asm("fma.rn.f32x2 %0, %1, %2, %0;" : "+l"(d) : "l"(a), "l"(b));
}
__device__ __forceinline__ float sigm(float x) { return 1.0f / (1.0f + __expf(-x)); }

// ============================================================================
// U transpose: g_uT[g][k][j] = U_g[j][k]
// ============================================================================
__global__ void transpose_u(const float* __restrict__ Uz,
                            const float* __restrict__ Ur,
                            const float* __restrict__ Uh)
{
    __shared__ float tile[32][33];
    const int g = blockIdx.z;
    const float* U = (g == 0) ? Uz : (g == 1) ? Ur : Uh;
    const int x0 = blockIdx.x * 32, y0 = blockIdx.y * 32;
    tile[threadIdx.y][threadIdx.x] = U[(y0 + threadIdx.y) * 256 + x0 + threadIdx.x];
    __syncthreads();
    g_uT[g * 65536 + (x0 + threadIdx.y) * 256 + (y0 + threadIdx.x)] =
        tile[threadIdx.x][threadIdx.y];
}

// ============================================================================
// SGEMM-NT with bias (unchanged from round 1; near f32x2 compute cap)
// ============================================================================
__global__ void __launch_bounds__(256) sgemm_nt_bias(
    const float* __restrict__ A, const float* __restrict__ Bw,
    const float* __restrict__ bias1, const float* __restrict__ bias2,
    float* __restrict__ C, int ldc, int coloff)
{
    __shared__ __align__(16) float As[16][132];
    __shared__ __align__(16) float Bs[16][132];
    const int t  = threadIdx.x;
    const int tm = t >> 4;
    const int tn = t & 15;

    ull acc[8][4];
#pragma unroll
    for (int i = 0; i < 8; i++)
#pragma unroll
        for (int j = 0; j < 4; j++) acc[i][j] = 0ULL;

    const float* Ab = A  + (size_t)blockIdx.x * 128 * 256;
    const float* Bb = Bw + (size_t)blockIdx.y * 128 * 256;
    const int lr = t >> 2;
    const int lk = (t & 3) << 2;

    for (int k0 = 0; k0 < 256; k0 += 16) {
        float4 a0 = *(const float4*)(Ab + (size_t)lr * 256 + k0 + lk);
        float4 a1 = *(const float4*)(Ab + (size_t)(lr + 64) * 256 + k0 + lk);
        float4 b0 = *(const float4*)(Bb + (size_t)lr * 256 + k0 + lk);
        float4 b1 = *(const float4*)(Bb + (size_t)(lr + 64) * 256 + k0 + lk);
        __syncthreads();
        As[lk + 0][lr] = a0.x; As[lk + 1][lr] = a0.y;
        As[lk + 2][lr] = a0.z; As[lk + 3][lr] = a0.w;
        As[lk + 0][lr + 64] = a1.x; As[lk + 1][lr + 64] = a1.y;
        As[lk + 2][lr + 64] = a1.z; As[lk + 3][lr + 64] = a1.w;
        Bs[lk + 0][lr] = b0.x; Bs[lk + 1][lr] = b0.y;
        Bs[lk + 2][lr] = b0.z; Bs[lk + 3][lr] = b0.w;
        Bs[lk + 0][lr + 64] = b1.x; Bs[lk + 1][lr + 64] = b1.y;
        Bs[lk + 2][lr + 64] = b1.z; Bs[lk + 3][lr + 64] = b1.w;
        __syncthreads();
#pragma unroll
        for (int kk = 0; kk < 16; kk++) {
            float4 av0 = *(const float4*)(&As[kk][tm * 8]);
            float4 av1 = *(const float4*)(&As[kk][tm * 8 + 4]);
            const ull* bp = (const ull*)(&Bs[kk][tn * 8]);
            ull b2_0 = bp[0], b2_1 = bp[1], b2_2 = bp[2], b2_3 = bp[3];
            float av[8] = {av0.x, av0.y, av0.z, av0.w, av1.x, av1.y, av1.z, av1.w};
#pragma unroll
            for (int i = 0; i < 8; i++) {
                ull a2 = pk2(av[i], av[i]);
                fma2(acc[i][0], a2, b2_0);
                fma2(acc[i][1], a2, b2_1);
                fma2(acc[i][2], a2, b2_2);
                fma2(acc[i][3], a2, b2_3);
            }
        }
    }

    const int row0 = blockIdx.x * 128 + tm * 8;
    const int col0 = blockIdx.y * 128 + tn * 8;
#pragma unroll
    for (int i = 0; i < 8; i++) {
#pragma unroll
        for (int j = 0; j < 4; j++) {
            float lo, hi;
            asm("mov.b64 {%0, %1}, %2;" : "=f"(lo), "=f"(hi) : "l"(acc[i][j]));
            int n0 = col0 + j * 2;
            float e0 = bias1[n0]     + (bias2 ? bias2[n0]     : 0.0f);
            float e1 = bias1[n0 + 1] + (bias2 ? bias2[n0 + 1] : 0.0f);
            C[(size_t)(row0 + i) * ldc + coloff + n0]     = lo + e0;
            C[(size_t)(row0 + i) * ldc + coloff + n0 + 1] = hi + e1;
        }
    }
}

// ============================================================================
// GRU scan v2: 64 CTAs x 4 batch rows x 512 threads (k-split x8).
// Thread (jg, kh): jg=t&63 owns cols [4jg,4jg+4); kh=t>>6 owns k in [32kh,32kh+32).
// z and h state live in the reducing thread's registers; SMEM holds the
// duplicated-f32x2 h broadcast, r*h broadcast, partial-sum buffer, and a
// 128KB pinned slice of Uz/Ur (k<64).
// ============================================================================
#define SM_FLOATS 52224   // 2*16384 pin + 16384 red + 2048 hdup + 1024 srh
#define SM_BYTES  (SM_FLOATS * 4)

// phase-1 inner loop: 32 k-steps, 2-deep U prefetch, 1-deep h prefetch.
// zp/rp pre-offset by (kb*256 + c0); hp pre-offset by kb*4.
__device__ __forceinline__ void p1_loop(const float* zp, const float* rp,
                                        const ull* hp, ull az[4][2], ull ar[4][2])
{
    ulonglong2 uz0 = *(const ulonglong2*)(zp);
    ulonglong2 ur0 = *(const ulonglong2*)(rp);
    ulonglong2 uz1 = *(const ulonglong2*)(zp + 256);
    ulonglong2 ur1 = *(const ulonglong2*)(rp + 256);
    ulonglong2 ha  = *(const ulonglong2*)(hp);
    ulonglong2 hb  = *(const ulonglong2*)(hp + 2);
#pragma unroll
    for (int kk = 0; kk < 32; kk++) {
        ulonglong2 uzn = uz1, urn = ur1, han = ha, hbn = hb;
        if (kk < 30) {
            uzn = *(const ulonglong2*)(zp + (kk + 2) * 256);
            urn = *(const ulonglong2*)(rp + (kk + 2) * 256);
        }
        if (kk < 31) {
            han = *(const ulonglong2*)(hp + (kk + 1) * 4);
            hbn = *(const ulonglong2*)(hp + (kk + 1) * 4 + 2);
        }
        fma2(az[0][0], uz0.x, ha.x); fma2(az[0][1], uz0.y, ha.x);
        fma2(az[1][0], uz0.x, ha.y); fma2(az[1][1], uz0.y, ha.y);
        fma2(az[2][0], uz0.x, hb.x); fma2(az[2][1], uz0.y, hb.x);
        fma2(az[3][0], uz0.x, hb.y); fma2(az[3][1], uz0.y, hb.y);
        fma2(ar[0][0], ur0.x, ha.x); fma2(ar[0][1], ur0.y, ha.x);
        fma2(ar[1][0], ur0.x, ha.y); fma2(ar[1][1], ur0.y, ha.y);
        fma2(ar[2][0], ur0.x, hb.x); fma2(ar[2][1], ur0.y, hb.x);
        fma2(ar[3][0], ur0.x, hb.y); fma2(ar[3][1], ur0.y, hb.y);
        uz0 = uz1; ur0 = ur1; uz1 = uzn; ur1 = urn;
        ha = han; hb = hbn;
    }
}

__global__ void __launch_bounds__(512, 1) gru_scan2(const int* __restrict__ x)
{
    extern __shared__ float sm[];
    float* pin_z = sm;                          // 16384 floats (Uz_T, k<64)
    float* pin_r = sm + 16384;                  // 16384 floats (Ur_T, k<64)
    float* red   = sm + 32768;                  // 16384: [kh][g][m][256col]
    ull*   hdup  = (ull*)(sm + 49152);          // 1024 ull: [col][m] pk2(h,h)
    float* srh4  = sm + 51200;                  // 1024: [col][m] r*h

    const int t  = threadIdx.x;
    const int jg = t & 63, c0 = jg * 4;
    const int kh = t >> 6, kb = kh * 32;
    const int b0 = blockIdx.x * 4;

    const float* uzT = g_uT;
    const float* urT = g_uT + 65536;
    const float* uhT = g_uT + 131072;

    // init pinned U slice + state
    for (int i = t; i < 4096; i += 512) {
        ((float4*)pin_z)[i] = ((const float4*)uzT)[i];
        ((float4*)pin_r)[i] = ((const float4*)urT)[i];
    }
    for (int i = t; i < 1024; i += 512) { hdup[i] = 0ULL; srh4[i] = 0.0f; }
    __syncthreads();

    // reducing-thread identity: unit0 = (m0, col0), unit1 = (m0+2, col0)
    const int m0 = t >> 8, col0 = t & 255;
    const int m1 = m0 + 2;
    float hold0 = 0.0f, hold1 = 0.0f;

    const float* zsrc = (kh < 2) ? (pin_z + kb * 256 + c0) : (uzT + kb * 256 + c0);
    const float* rsrc = (kh < 2) ? (pin_r + kb * 256 + c0) : (urT + kb * 256 + c0);
    const float* hsrc = uhT + kb * 256 + c0;

    for (int s = 0; s < SSZ; s++) {
        // ---------------- phase 1: z, r partials ----------------
        ull az[4][2], ar[4][2];
#pragma unroll
        for (int m = 0; m < 4; m++) {
            az[m][0] = az[m][1] = 0ULL;
            ar[m][0] = ar[m][1] = 0ULL;
        }
        if (kh < 2) p1_loop(zsrc, rsrc, hdup + kb * 4, az, ar);
        else        p1_loop(zsrc, rsrc, hdup + kb * 4, az, ar);

#pragma unroll
        for (int m = 0; m < 4; m++) {
            *(ulonglong2*)(red + (kh * 8 + m) * 256 + c0)     =
                make_ulonglong2(az[m][0], az[m][1]);
            *(ulonglong2*)(red + (kh * 8 + 4 + m) * 256 + c0) =
                make_ulonglong2(ar[m][0], ar[m][1]);
        }
        __syncthreads();

        // ---------------- reduce 1: z, r, srh ----------------
        const int tok0 = __ldg(&x[(size_t)(b0 + m0) * SSZ + s]);
        const int tok1 = __ldg(&x[(size_t)(b0 + m1) * SSZ + s]);
        const float* e0 = g_eproj + (size_t)tok0 * 768;
        const float* e1 = g_eproj + (size_t)tok1 * 768;

        float sz0 = 0.f, sr0 = 0.f, sz1 = 0.f, sr1 = 0.f;
#pragma unroll
        for (int q = 0; q < 8; q++) {
            sz0 += red[(q * 8 + m0) * 256 + col0];
            sr0 += red[(q * 8 + 4 + m0) * 256 + col0];
            sz1 += red[(q * 8 + m1) * 256 + col0];
            sr1 += red[(q * 8 + 4 + m1) * 256 + col0];
        }
        const float z0 = sigm(sz0 + __ldg(e0 + col0));
        const float r0 = sigm(sr0 + __ldg(e0 + 256 + col0));
        const float z1 = sigm(sz1 + __ldg(e1 + col0));
        const float r1 = sigm(sr1 + __ldg(e1 + 256 + col0));
        srh4[col0 * 4 + m0] = r0 * hold0;
        srh4[col0 * 4 + m1] = r1 * hold1;
        __syncthreads();

        // ---------------- phase 2: h_tilde partials ----------------
        ull ah[4][2];
#pragma unroll
        for (int m = 0; m < 4; m++) { ah[m][0] = ah[m][1] = 0ULL; }
        {
            const float* sp = srh4 + kb * 4;
            ulonglong2 uh0 = *(const ulonglong2*)(hsrc);
            ulonglong2 uh1 = *(const ulonglong2*)(hsrc + 256);
            float4 sv = *(const float4*)(sp);
#pragma unroll
            for (int kk = 0; kk < 32; kk++) {
                ulonglong2 uhn = uh1;
                float4 svn = sv;
                if (kk < 30) uhn = *(const ulonglong2*)(hsrc + (kk + 2) * 256);
                if (kk < 31) svn = *(const float4*)(sp + (kk + 1) * 4);
                ull s0 = pk2(sv.x, sv.x), s1 = pk2(sv.y, sv.y);
                ull s2 = pk2(sv.z, sv.z), s3 = pk2(sv.w, sv.w);
                fma2(ah[0][0], uh0.x, s0); fma2(ah[0][1], uh0.y, s0);
                fma2(ah[1][0], uh0.x, s1); fma2(ah[1][1], uh0.y, s1);
                fma2(ah[2][0], uh0.x, s2); fma2(ah[2][1], uh0.y, s2);
                fma2(ah[3][0], uh0.x, s3); fma2(ah[3][1], uh0.y, s3);
                uh0 = uh1; uh1 = uhn; sv = svn;
            }
        }
#pragma unroll
        for (int m = 0; m < 4; m++)
            *(ulonglong2*)(red + (kh * 8 + m) * 256 + c0) =
                make_ulonglong2(ah[m][0], ah[m][1]);
        __syncthreads();

        // ---------------- reduce 2: h update ----------------
        float sh0 = 0.f, sh1 = 0.f;
#pragma unroll
        for (int q = 0; q < 8; q++) {
            sh0 += red[(q * 8 + m0) * 256 + col0];
            sh1 += red[(q * 8 + m1) * 256 + col0];
        }
        const float ht0 = tanhf(sh0 + __ldg(e0 + 512 + col0));
        const float ht1 = tanhf(sh1 + __ldg(e1 + 512 + col0));
        hold0 += z0 * (ht0 - hold0);
        hold1 += z1 * (ht1 - hold1);
        hdup[col0 * 4 + m0] = pk2(hold0, hold0);
        hdup[col0 * 4 + m1] = pk2(hold1, hold1);
        __syncthreads();
    }

    g_hlast[(size_t)(b0 + m0) * HSZ + col0] = hold0;
    g_hlast[(size_t)(b0 + m1) * HSZ + col0] = hold1;
}

// ============================================================================
extern "C" void kernel_launch(void* const* d_in, const int* in_sizes, int n_in,
                              void* d_out, int out_size)
{
    const int*   x   = (const int*)  d_in[0];
    const float* emb = (const float*)d_in[1];
    const float* Wz  = (const float*)d_in[2];
    const float* bz  = (const float*)d_in[3];
    const float* Uz  = (const float*)d_in[4];
    const float* buz = (const float*)d_in[5];
    const float* Wr  = (const float*)d_in[6];
    const float* br  = (const float*)d_in[7];
    const float* Ur  = (const float*)d_in[8];
    const float* bur = (const float*)d_in[9];
    const float* Wh  = (const float*)d_in[10];
    const float* bh  = (const float*)d_in[11];
    const float* Uh  = (const float*)d_in[12];
    const float* buh = (const float*)d_in[13];
    const float* Wf  = (const float*)d_in[14];
    const float* bf  = (const float*)d_in[15];
    float* out = (float*)d_out;

    float* eproj = nullptr;
    float* hlast = nullptr;
    cudaGetSymbolAddress((void**)&eproj, g_eproj);
    cudaGetSymbolAddress((void**)&hlast, g_hlast);

    cudaFuncSetAttribute(gru_scan2,
                         cudaFuncAttributeMaxDynamicSharedMemorySize, SM_BYTES);

    dim3 blk(256);
    transpose_u<<<dim3(8, 8, 3), dim3(32, 32)>>>(Uz, Ur, Uh);
    sgemm_nt_bias<<<dim3(250, 2), blk>>>(emb, Wz, bz, buz, eproj, 768, 0);
    sgemm_nt_bias<<<dim3(250, 2), blk>>>(emb, Wr, br, bur, eproj, 768, 256);
    sgemm_nt_bias<<<dim3(250, 2), blk>>>(emb, Wh, bh, buh, eproj, 768, 512);

    gru_scan2<<<64, 512, SM_BYTES>>>(x);

    sgemm_nt_bias<<<dim3(2, 250), blk>>>(hlast, Wf, bf, nullptr, out, 32000, 0);
}